// round 13
// baseline (speedup 1.0000x reference)
#include <cuda_runtime.h>
#include <cuda_bf16.h>

// ConnectedWithinCutoff: B=64 graphs, n=512 nodes each.
// Output (float32, concatenated in reference return order):
//   [0, B*n*n*2)                 edge_index_all as floats (src,dst interleaved)
//   [B*n*n*2, B*n*n*3)           edge_mask as 0.0/1.0
//   [B*n*n*3, B*n*n*3 + B)       num_edges per graph
//   [B*n*n*3 + B, ... + B*n*n)   distances [B,n,n]
//
// Steady-state DRAM-write bound (~4.95 TB/s wall, ~42us floor). evict_last
// retention is way-quota-capped; pin-size sweep (134/96/60MB -> 43.7/43.5/43.1)
// improves monotonically as the set shrinks toward the quota. This round:
// PIN_B=24 (48MB) — one more step down the curve to locate the knee.

#define CUTOFF_F 5.0f
#define BLOCK_THREADS 256
#define MAX_B 1024
#define PIN_B 24   // 24 graphs * 2MB eidx = 48MB pinned

// Self-resetting per-graph reduction state (zero at module load; the last
// arriving block per graph resets it each launch → clean state every replay).
__device__ int g_sum[MAX_B];
__device__ int g_arrived[MAX_B];

// evict-first streaming store (mask / dist)
__device__ __forceinline__ void st_cs(float* p, float a, float b, float c, float d) {
    asm volatile("st.global.cs.v4.f32 [%0], {%1,%2,%3,%4};"
                 :: "l"(p), "f"(a), "f"(b), "f"(c), "f"(d) : "memory");
}
// 256-bit evict-last store (pinned eidx: dirty lines L2-resident across replays)
__device__ __forceinline__ void st_el8(float* p,
                                       float a, float b, float c, float d,
                                       float e, float f, float g, float h) {
    asm volatile("st.global.L2::evict_last.v8.b32 [%0], {%1,%2,%3,%4,%5,%6,%7,%8};"
                 :: "l"(p),
                    "r"(__float_as_uint(a)), "r"(__float_as_uint(b)),
                    "r"(__float_as_uint(c)), "r"(__float_as_uint(d)),
                    "r"(__float_as_uint(e)), "r"(__float_as_uint(f)),
                    "r"(__float_as_uint(g)), "r"(__float_as_uint(h)) : "memory");
}
// 256-bit evict-first store (unpinned eidx: same instruction form, stream policy)
__device__ __forceinline__ void st_ef8(float* p,
                                       float a, float b, float c, float d,
                                       float e, float f, float g, float h) {
    asm volatile("st.global.L2::evict_first.v8.b32 [%0], {%1,%2,%3,%4,%5,%6,%7,%8};"
                 :: "l"(p),
                    "r"(__float_as_uint(a)), "r"(__float_as_uint(b)),
                    "r"(__float_as_uint(c)), "r"(__float_as_uint(d)),
                    "r"(__float_as_uint(e)), "r"(__float_as_uint(f)),
                    "r"(__float_as_uint(g)), "r"(__float_as_uint(h)) : "memory");
}

template<int N, int I_TILE>
__global__ __launch_bounds__(BLOCK_THREADS, 6)
void cwc_main_t(const float* __restrict__ pos,
                float* __restrict__ outEidx,
                float* __restrict__ outMask,
                float* __restrict__ outNe,
                float* __restrict__ outDist,
                int tilesPerGraph)
{
    __shared__ __align__(16) float sx[N];
    __shared__ __align__(16) float sy[N];
    __shared__ __align__(16) float sz[N];
    __shared__ int sCnt;

    const int b   = blockIdx.x / tilesPerGraph;
    const int i0  = (blockIdx.x % tilesPerGraph) * I_TILE;
    const int tid = threadIdx.x;

    if (tid == 0) sCnt = 0;

    // Stage this graph's positions into shared (SoA).
    const float* gp = pos + (size_t)b * N * 3;
    #pragma unroll
    for (int idx = tid; idx < N; idx += BLOCK_THREADS) {
        sx[idx] = gp[idx * 3 + 0];
        sy[idx] = gp[idx * 3 + 1];
        sz[idx] = gp[idx * 3 + 2];
    }
    __syncthreads();

    const int tx = tid & 127;   // j-group: j = tx*4 .. tx*4+3  (N=512 → full row)
    const int ty = tid >> 7;    // row phase (0 or 1)
    const int j  = tx * 4;

    constexpr size_t NN = (size_t)N * N;

    // Hoist the 4 j-node positions into registers: 3x LDS.128, once.
    const float4 jx = *reinterpret_cast<const float4*>(&sx[j]);
    const float4 jy = *reinterpret_cast<const float4*>(&sy[j]);
    const float4 jz = *reinterpret_cast<const float4*>(&sz[j]);

    // Per-thread base pointers; loop offsets are compile-time constants.
    const size_t rb0 = (size_t)b * NN + (size_t)(i0 + ty) * N + (size_t)j;
    float* pd = outDist + rb0;
    float* pm = outMask + rb0;
    float* pe = outEidx + rb0 * 2;   // 32B-aligned: rb0 % 4 == 0

    const float fb   = (float)(b * N);
    const float dstb = fb + (float)j;
    float src = fb + (float)(i0 + ty);

    const bool pinned = (b < PIN_B);   // uniform per block
    float fcnt = 0.0f;

    #pragma unroll
    for (int k = 0; k < I_TILE / 2; k++) {
        const int i = i0 + ty + 2 * k;
        const float xi = sx[i], yi = sy[i], zi = sz[i];

        float dx, dy, dz;
        dx = xi - jx.x; dy = yi - jy.x; dz = zi - jz.x;
        const float d0 = sqrtf(dx*dx + dy*dy + dz*dz);
        dx = xi - jx.y; dy = yi - jy.y; dz = zi - jz.y;
        const float d1 = sqrtf(dx*dx + dy*dy + dz*dz);
        dx = xi - jx.z; dy = yi - jy.z; dz = zi - jz.z;
        const float d2 = sqrtf(dx*dx + dy*dy + dz*dz);
        dx = xi - jx.w; dy = yi - jy.w; dz = zi - jz.w;
        const float d3 = sqrtf(dx*dx + dy*dy + dz*dz);

        const float m0 = (d0 <= CUTOFF_F && (j+0) != i) ? 1.0f : 0.0f;
        const float m1 = (d1 <= CUTOFF_F && (j+1) != i) ? 1.0f : 0.0f;
        const float m2 = (d2 <= CUTOFF_F && (j+2) != i) ? 1.0f : 0.0f;
        const float m3 = (d3 <= CUTOFF_F && (j+3) != i) ? 1.0f : 0.0f;
        fcnt += (m0 + m1) + (m2 + m3);

        // stream mask+dist to DRAM (evict-first)
        st_cs(pd + (size_t)(2 * k) * N, d0, d1, d2, d3);
        st_cs(pm + (size_t)(2 * k) * N, m0, m1, m2, m3);

        // edge_index: same v8 store form, policy differs by pin predicate
        float* peq = pe + (size_t)(4 * k) * N;
        if (pinned) {
            st_el8(peq,
                   src, dstb + 0.0f, src, dstb + 1.0f,
                   src, dstb + 2.0f, src, dstb + 3.0f);
        } else {
            st_ef8(peq,
                   src, dstb + 0.0f, src, dstb + 1.0f,
                   src, dstb + 2.0f, src, dstb + 3.0f);
        }

        src += 2.0f;
    }

    // block-level edge count
    int cnt = (int)fcnt;
    #pragma unroll
    for (int off = 16; off > 0; off >>= 1)
        cnt += __shfl_down_sync(0xffffffffu, cnt, off);
    if ((tid & 31) == 0 && cnt > 0)
        atomicAdd(&sCnt, cnt);
    __syncthreads();

    // last-arriving block per graph publishes num_edges and resets state
    if (tid == 0) {
        atomicAdd(&g_sum[b], sCnt);
        __threadfence();
        int old = atomicAdd(&g_arrived[b], 1);
        if (old == tilesPerGraph - 1) {
            int tot = atomicExch(&g_sum[b], 0);
            atomicExch(&g_arrived[b], 0);
            outNe[b] = (float)tot;
        }
    }
}

// -------- generic fallback (any n that is a multiple of 4, n <= 512) --------
__global__ void cwc_generic(const float* __restrict__ pos,
                            float* __restrict__ out,
                            int B, int n, int tilesPerGraph)
{
    __shared__ __align__(16) float sx[512];
    __shared__ __align__(16) float sy[512];
    __shared__ __align__(16) float sz[512];
    __shared__ int sCnt;

    const int b   = blockIdx.x / tilesPerGraph;
    const int i0  = (blockIdx.x % tilesPerGraph) * 8;
    const int tid = threadIdx.x;
    if (tid == 0) sCnt = 0;

    const float* gp = pos + (size_t)b * n * 3;
    for (int idx = tid; idx < n; idx += 256) {
        sx[idx] = gp[idx * 3 + 0];
        sy[idx] = gp[idx * 3 + 1];
        sz[idx] = gp[idx * 3 + 2];
    }
    __syncthreads();

    const int tx = tid & 127, ty = tid >> 7, j = tx * 4;
    const size_t nn = (size_t)n * n;
    const size_t maskBase = (size_t)B * nn * 2;
    const size_t neBase   = maskBase + (size_t)B * nn;
    const size_t distBase = neBase + (size_t)B;
    const float fb = (float)(b * n);
    int cnt = 0;

    if (j < n) {
        for (int r = ty; r < 8; r += 2) {
            const int i = i0 + r;
            if (i >= n) break;
            const float xi = sx[i], yi = sy[i], zi = sz[i];
            float d[4], m[4];
            #pragma unroll
            for (int q = 0; q < 4; q++) {
                float dx = xi - sx[j+q], dy = yi - sy[j+q], dz = zi - sz[j+q];
                d[q] = sqrtf(dx*dx + dy*dy + dz*dz);
                m[q] = (d[q] <= CUTOFF_F && (j+q) != i) ? 1.0f : 0.0f;
                cnt += (int)m[q];
            }
            const size_t rowBase = (size_t)b * nn + (size_t)i * n + (size_t)j;
            *reinterpret_cast<float4*>(out + distBase + rowBase) = make_float4(d[0],d[1],d[2],d[3]);
            *reinterpret_cast<float4*>(out + maskBase + rowBase) = make_float4(m[0],m[1],m[2],m[3]);
            const float src = fb + (float)i, dstb = fb + (float)j;
            *reinterpret_cast<float4*>(out + rowBase*2)     = make_float4(src, dstb+0.f, src, dstb+1.f);
            *reinterpret_cast<float4*>(out + rowBase*2 + 4) = make_float4(src, dstb+2.f, src, dstb+3.f);
        }
    }
    #pragma unroll
    for (int off = 16; off > 0; off >>= 1)
        cnt += __shfl_down_sync(0xffffffffu, cnt, off);
    if ((tid & 31) == 0 && cnt > 0) atomicAdd(&sCnt, cnt);
    __syncthreads();
    if (tid == 0) {
        atomicAdd(&g_sum[b], sCnt);
        __threadfence();
        int old = atomicAdd(&g_arrived[b], 1);
        if (old == tilesPerGraph - 1) {
            int tot = atomicExch(&g_sum[b], 0);
            atomicExch(&g_arrived[b], 0);
            out[neBase + b] = (float)tot;
        }
    }
}

extern "C" void kernel_launch(void* const* d_in, const int* in_sizes, int n_in,
                              void* d_out, int out_size) {
    // inputs: [0] num_nodes int32 [B], [1] positions float32 [B*n, 3]
    const float* pos = (const float*)d_in[1];
    float* out = (float*)d_out;

    const int B = in_sizes[0];
    const int n = in_sizes[1] / (3 * B);

    if (n == 512) {
        constexpr int N = 512, I_TILE = 8;
        const size_t NN = (size_t)N * N;
        float* outEidx = out;
        float* outMask = out + (size_t)B * NN * 2;
        float* outNe   = out + (size_t)B * NN * 3;
        float* outDist = outNe + B;
        const int tilesPerGraph = N / I_TILE;          // 64
        const int grid = B * tilesPerGraph;            // 4096
        cwc_main_t<N, I_TILE><<<grid, BLOCK_THREADS>>>(
            pos, outEidx, outMask, outNe, outDist, tilesPerGraph);
    } else {
        const int tilesPerGraph = (n + 7) / 8;
        cwc_generic<<<B * tilesPerGraph, 256>>>(pos, out, B, n, tilesPerGraph);
    }
}